// round 3
// baseline (speedup 1.0000x reference)
#include <cuda_runtime.h>
#include <stdint.h>

// SeqOperation: out[b,i,:] = seq[b,p,:]     if i == (p+1) % n         (ungated)
//                          = seq[b,i,:]     if p<=n-3 && i < p
//                          = seq[b,i-2,:]   if p<=n-3 && i >= p+3
//                          = 0              otherwise
// p = pos_idx[b]. Shapes: seq (B=4096, n=200, d=128) f32; pos_idx (B,).
// NOTE: pos_idx is int32 on device (JAX x64 disabled downcasts jnp.int64).
// Pure bandwidth problem: ~838 MB traffic -> target ~130-170 us on GB300.

constexpr int N_SEQ = 200;
constexpr int D4    = 32;   // d=128 floats = 32 float4 per row
constexpr int ROWS_PER_BLOCK = 8;   // 256 threads / 32 lanes

__global__ __launch_bounds__(256)
void seqop_kernel(const float4* __restrict__ seq,
                  const int* __restrict__ pos_idx,
                  float4* __restrict__ out,
                  int total_rows)
{
    int row  = blockIdx.x * ROWS_PER_BLOCK + (threadIdx.x >> 5);
    int lane = threadIdx.x & 31;
    if (row >= total_rows) return;

    int b = row / N_SEQ;
    int i = row - b * N_SEQ;

    int p = __ldg(&pos_idx[b]);
    bool valid = (p <= N_SEQ - 3);
    int pp1 = (p + 1 == N_SEQ) ? 0 : (p + 1);

    int src = -1;
    if (i == pp1) {
        src = p;                       // rolled "pos" term, NOT gated by valid
    } else if (valid) {
        if (i < p)            src = i;       // left term
        else if (i >= p + 3)  src = i - 2;   // rolled "right" term
    }

    float4 v = make_float4(0.f, 0.f, 0.f, 0.f);
    if (src >= 0) {
        v = __ldg(&seq[(b * N_SEQ + src) * D4 + lane]);
    }
    out[row * D4 + lane] = v;   // always write: d_out is poisoned
}

extern "C" void kernel_launch(void* const* d_in, const int* in_sizes, int n_in,
                              void* d_out, int out_size)
{
    const float4* seq = (const float4*)d_in[0];
    const int*    pos = (const int*)d_in[1];
    float4*       o   = (float4*)d_out;

    int B = in_sizes[1];                 // 4096
    int total_rows = B * N_SEQ;          // 819200

    int grid = (total_rows + ROWS_PER_BLOCK - 1) / ROWS_PER_BLOCK;
    seqop_kernel<<<grid, 256>>>(seq, pos, o, total_rows);
}

// round 5
// speedup vs baseline: 1.1818x; 1.1818x over previous
#include <cuda_runtime.h>
#include <stdint.h>

// SeqOperation: out[b,i,:] = seq[b,p,:]     if i == (p+1) % n         (ungated)
//                          = seq[b,i,:]     if p<=n-3 && i < p
//                          = seq[b,i-2,:]   if p<=n-3 && i >= p+3
//                          = 0              otherwise
// p = pos_idx[b] (int32 on device). seq: (B=4096, n=200, d=128) f32.
// Bandwidth-bound: ~838 MB traffic. R3 = 145.8us @ 69.8% DRAM with MLP=1.
// This round: 2 rows per warp, loads front-batched (MLP_p1=2) to hide DRAM latency.

constexpr int N_SEQ = 200;
constexpr int D4    = 32;            // d=128 floats = 32 float4 per row
constexpr int ROWS_PER_WARP  = 2;
constexpr int WARPS_PER_BLOCK = 8;   // 256 threads
constexpr int ROWS_PER_BLOCK = ROWS_PER_WARP * WARPS_PER_BLOCK;  // 16

__device__ __forceinline__ int src_row(int i, int p)
{
    // returns source row index within batch, or -1 for zero-fill
    bool valid = (p <= N_SEQ - 3);
    int pp1 = (p + 1 == N_SEQ) ? 0 : (p + 1);
    if (i == pp1) return p;                    // rolled "pos" term, NOT gated
    if (valid) {
        if (i < p)     return i;               // left term
        if (i >= p + 3) return i - 2;          // rolled "right" term
    }
    return -1;
}

__global__ __launch_bounds__(256)
void seqop_kernel(const float4* __restrict__ seq,
                  const int* __restrict__ pos_idx,
                  float4* __restrict__ out,
                  int total_rows)
{
    int warp = blockIdx.x * WARPS_PER_BLOCK + (threadIdx.x >> 5);
    int lane = threadIdx.x & 31;
    int r0   = warp * ROWS_PER_WARP;
    if (r0 >= total_rows) return;

    int  src[ROWS_PER_WARP];
    int  row[ROWS_PER_WARP];

    #pragma unroll
    for (int k = 0; k < ROWS_PER_WARP; k++) {
        int r = r0 + k;
        row[k] = r;
        int b = r / N_SEQ;
        int i = r - b * N_SEQ;
        int p = __ldg(&pos_idx[b]);
        src[k] = src_row(i, p);
        if (src[k] >= 0) src[k] += b * N_SEQ;   // absolute source row
    }

    // Front-batch both loads so they are concurrently in flight (MLP=2).
    float4 v[ROWS_PER_WARP];
    #pragma unroll
    for (int k = 0; k < ROWS_PER_WARP; k++) {
        v[k] = make_float4(0.f, 0.f, 0.f, 0.f);
        if (src[k] >= 0)
            v[k] = __ldg(&seq[src[k] * D4 + lane]);
    }

    #pragma unroll
    for (int k = 0; k < ROWS_PER_WARP; k++) {
        out[row[k] * D4 + lane] = v[k];          // always write: d_out poisoned
    }
}

extern "C" void kernel_launch(void* const* d_in, const int* in_sizes, int n_in,
                              void* d_out, int out_size)
{
    const float4* seq = (const float4*)d_in[0];
    const int*    pos = (const int*)d_in[1];
    float4*       o   = (float4*)d_out;

    int B = in_sizes[1];                 // 4096
    int total_rows = B * N_SEQ;          // 819200

    int grid = (total_rows + ROWS_PER_BLOCK - 1) / ROWS_PER_BLOCK;  // 51200
    seqop_kernel<<<grid, 256>>>(seq, pos, o, total_rows);
}